// round 4
// baseline (speedup 1.0000x reference)
#include <cuda_runtime.h>
#include <cuda_bf16.h>
#include <cstdint>

#define M_TOT   8192
#define K_IN    4096
#define RANK    256
#define N_OUT   4096
#define VERA_SCALE (32.0f / 256.0f)

// rank-space intermediate t = (x @ A^T) * d_A : [M_TOT][RANK]
__device__ float g_t[(size_t)M_TOT * RANK];

// ------------- helpers -------------
__device__ __forceinline__ uint32_t smem_u32(const void* p) {
    uint32_t a;
    asm("{ .reg .u64 t; cvta.to.shared.u64 t, %1; cvt.u32.u64 %0, t; }" : "=r"(a) : "l"(p));
    return a;
}
__device__ __forceinline__ void ldsm4(uint32_t r[4], uint32_t addr) {
    asm volatile("ldmatrix.sync.aligned.m8n8.x4.shared.b16 {%0,%1,%2,%3}, [%4];"
                 : "=r"(r[0]), "=r"(r[1]), "=r"(r[2]), "=r"(r[3]) : "r"(addr));
}
__device__ __forceinline__ void mma_bf16(float c[4], const uint32_t a[4],
                                         uint32_t b0, uint32_t b1) {
    asm volatile(
        "mma.sync.aligned.m16n8k16.row.col.f32.bf16.bf16.f32 "
        "{%0,%1,%2,%3}, {%4,%5,%6,%7}, {%8,%9}, {%0,%1,%2,%3};"
        : "+f"(c[0]), "+f"(c[1]), "+f"(c[2]), "+f"(c[3])
        : "r"(a[0]), "r"(a[1]), "r"(a[2]), "r"(a[3]), "r"(b0), "r"(b1));
}
__device__ __forceinline__ uint32_t pk(__nv_bfloat16 a, __nv_bfloat16 b) {
    return (uint32_t)__bfloat16_as_ushort(a) | ((uint32_t)__bfloat16_as_ushort(b) << 16);
}
__device__ __forceinline__ uint32_t sw128(uint32_t b) {
    return b ^ ((b >> 3) & 0x70);
}

// Load 128x64 fp32 tile (row stride ld) -> bf16 hi & lo SW128 tiles in smem.
__device__ __forceinline__ void load_cvt(const float* __restrict__ g, int ld,
                                         char* __restrict__ hi, char* __restrict__ lo,
                                         int tid) {
    #pragma unroll
    for (int it = 0; it < 8; ++it) {
        int idx = tid + it * 256;
        int row = idx >> 4;
        int c4  = (idx & 15) << 2;
        float4 v = *reinterpret_cast<const float4*>(g + (size_t)row * ld + c4);
        __nv_bfloat16 h0 = __float2bfloat16(v.x);
        __nv_bfloat16 h1 = __float2bfloat16(v.y);
        __nv_bfloat16 h2 = __float2bfloat16(v.z);
        __nv_bfloat16 h3 = __float2bfloat16(v.w);
        __nv_bfloat16 l0 = __float2bfloat16(v.x - __bfloat162float(h0));
        __nv_bfloat16 l1 = __float2bfloat16(v.y - __bfloat162float(h1));
        __nv_bfloat16 l2 = __float2bfloat16(v.z - __bfloat162float(h2));
        __nv_bfloat16 l3 = __float2bfloat16(v.w - __bfloat162float(h3));
        uint32_t off = sw128((uint32_t)(row * 128 + c4 * 2));
        uint2 hv; hv.x = pk(h0, h1); hv.y = pk(h2, h3);
        uint2 lv; lv.x = pk(l0, l1); lv.y = pk(l2, l3);
        *reinterpret_cast<uint2*>(hi + off) = hv;
        *reinterpret_cast<uint2*>(lo + off) = lv;
    }
}

// GEMM-NT: Out[m][n] = (sum_k X[m][k] * W[n][k]) * csc[n] * scale
// CTA tile 128x128, K-chunk 64, bf16x3 split precision on mma.sync,
// double-buffered SMEM with one barrier per chunk (loads overlap MMAs).
// 256 threads = 8 warps in a 4(m) x 2(n) grid; warp tile 32(m) x 64(n).
__global__ __launch_bounds__(256)
void vera_hmma(const float* __restrict__ X, const float* __restrict__ W,
               const float* __restrict__ csc, float scale, float* __restrict__ Out,
               int Ntot, int K)
{
    extern __shared__ char smem[];
    // two stages of {Xhi,Xlo,Whi,Wlo} each 16KB; cs after.
    constexpr int STAGE = 65536;
    float* cs = reinterpret_cast<float*>(smem + 2 * STAGE);
    const uint32_t sb = smem_u32(smem);

    const int tid = threadIdx.x;
    const int wid = tid >> 5;
    const int lid = tid & 31;
    const int warp_m = wid & 3;
    const int warp_n = wid >> 2;

    const int bm = blockIdx.x * 128;
    const int bn = blockIdx.y * 128;

    if (tid < 128) cs[tid] = csc[bn + tid] * scale;

    // per-lane ldmatrix offsets (within a stage)
    const int rowA = warp_m * 32 + (lid & 15);
    const uint32_t pA0 = (uint32_t)(rowA * 128);
    const uint32_t pA1 = pA0 + 16 * 128;
    const uint32_t kbA = (uint32_t)((lid >> 4) * 16);
    const uint32_t xA  = (uint32_t)((rowA & 7) << 4);
    const int rowB = warp_n * 64 + ((lid >> 4) * 8 + (lid & 7));
    const uint32_t pB0 = (uint32_t)(rowB * 128);
    const uint32_t kbB = (uint32_t)(((lid >> 3) & 1) * 16);
    const uint32_t xB  = (uint32_t)((rowB & 7) << 4);

    float acc[2][8][4];
    #pragma unroll
    for (int i = 0; i < 2; ++i)
        #pragma unroll
        for (int j = 0; j < 8; ++j)
            #pragma unroll
            for (int q = 0; q < 4; ++q)
                acc[i][j][q] = 0.0f;

    const int nchunks = K >> 6;
    const float* Xg = X + (size_t)bm * K;
    const float* Wg = W + (size_t)bn * K;

    // prologue: fill stage 0
    load_cvt(Xg, K, smem, smem + 16384, tid);
    load_cvt(Wg, K, smem + 32768, smem + 49152, tid);
    __syncthreads();

    for (int ch = 0; ch < nchunks; ++ch) {
        const int b = ch & 1;

        // producer phase for chunk ch+1 into the other stage (no barrier
        // before the MMAs -> LDG latency hides behind tensor work)
        if (ch + 1 < nchunks) {
            char* dst = smem + (b ^ 1) * STAGE;
            load_cvt(Xg + (ch + 1) * 64, K, dst, dst + 16384, tid);
            load_cvt(Wg + (ch + 1) * 64, K, dst + 32768, dst + 49152, tid);
        }

        // consumer phase on stage b
        const uint32_t base = sb + (uint32_t)(b * STAGE);
        #pragma unroll
        for (int s = 0; s < 4; ++s) {
            const uint32_t aoff = ((uint32_t)(s * 32) + kbA) ^ xA;
            const uint32_t boff = ((uint32_t)(s * 32) + kbB) ^ xB;
            uint32_t ah0[4], ah1[4], al0[4], al1[4];
            ldsm4(ah0, base + 0     + pA0 + aoff);
            ldsm4(ah1, base + 0     + pA1 + aoff);
            ldsm4(al0, base + 16384 + pA0 + aoff);
            ldsm4(al1, base + 16384 + pA1 + aoff);
            #pragma unroll
            for (int np = 0; np < 4; ++np) {
                uint32_t bh[4], bl[4];
                ldsm4(bh, base + 32768 + pB0 + (uint32_t)(np * 2048) + boff);
                ldsm4(bl, base + 49152 + pB0 + (uint32_t)(np * 2048) + boff);
                mma_bf16(acc[0][2 * np],     ah0, bh[0], bh[1]);
                mma_bf16(acc[1][2 * np],     ah1, bh[0], bh[1]);
                mma_bf16(acc[0][2 * np + 1], ah0, bh[2], bh[3]);
                mma_bf16(acc[1][2 * np + 1], ah1, bh[2], bh[3]);
                mma_bf16(acc[0][2 * np],     ah0, bl[0], bl[1]);
                mma_bf16(acc[1][2 * np],     ah1, bl[0], bl[1]);
                mma_bf16(acc[0][2 * np + 1], ah0, bl[2], bl[3]);
                mma_bf16(acc[1][2 * np + 1], ah1, bl[2], bl[3]);
                mma_bf16(acc[0][2 * np],     al0, bh[0], bh[1]);
                mma_bf16(acc[1][2 * np],     al1, bh[0], bh[1]);
                mma_bf16(acc[0][2 * np + 1], al0, bh[2], bh[3]);
                mma_bf16(acc[1][2 * np + 1], al1, bh[2], bh[3]);
            }
        }
        __syncthreads();
    }

    // epilogue
    const int mrow0 = bm + warp_m * 32 + (lid >> 2);
    const int nc0   = warp_n * 64 + (lid & 3) * 2;
    #pragma unroll
    for (int mi = 0; mi < 2; ++mi) {
        #pragma unroll
        for (int nj = 0; nj < 8; ++nj) {
            const int n = nc0 + nj * 8;
            const float s0 = cs[n], s1 = cs[n + 1];
            float2 v0, v1;
            v0.x = acc[mi][nj][0] * s0; v0.y = acc[mi][nj][1] * s1;
            v1.x = acc[mi][nj][2] * s0; v1.y = acc[mi][nj][3] * s1;
            const int m0 = mrow0 + mi * 16;
            *reinterpret_cast<float2*>(Out + (size_t)m0 * Ntot + bn + n) = v0;
            *reinterpret_cast<float2*>(Out + (size_t)(m0 + 8) * Ntot + bn + n) = v1;
        }
    }
}

extern "C" void kernel_launch(void* const* d_in, const int* in_sizes, int n_in,
                              void* d_out, int out_size)
{
    const float* x   = (const float*)d_in[0];  // [8192][4096]
    const float* A   = (const float*)d_in[1];  // [256][4096]
    const float* B   = (const float*)d_in[2];  // [4096][256]
    const float* d_A = (const float*)d_in[3];  // [256]
    const float* d_B = (const float*)d_in[4];  // [4096]
    float* out = (float*)d_out;                // [8192][4096]

    float* t = nullptr;
    cudaGetSymbolAddress((void**)&t, g_t);

    constexpr int SMEM = 2 * 65536 + 512;      // 131584
    cudaFuncSetAttribute(vera_hmma, cudaFuncAttributeMaxDynamicSharedMemorySize, SMEM);

    // GEMM1: t = (x @ A^T) * d_A      M=8192, N=256, K=4096
    {
        dim3 grid(M_TOT / 128, RANK / 128);   // 64 x 2
        vera_hmma<<<grid, 256, SMEM>>>(x, A, d_A, 1.0f, t, RANK, K_IN);
    }
    // GEMM2: out = (t @ B^T) * d_B * SCALE   M=8192, N=4096, K=256
    {
        dim3 grid(M_TOT / 128, N_OUT / 128);  // 64 x 32
        vera_hmma<<<grid, 256, SMEM>>>(t, B, d_B, VERA_SCALE, out, N_OUT, RANK);
    }
}

// round 5
// speedup vs baseline: 1.1020x; 1.1020x over previous
#include <cuda_runtime.h>
#include <cuda_bf16.h>
#include <cstdint>

#define M_TOT   8192
#define K_IN    4096
#define RANK    256
#define N_OUT   4096
#define VERA_SCALE (32.0f / 256.0f)

// rank-space intermediate t = (x @ A^T) * d_A : [M_TOT][RANK]
__device__ float g_t[(size_t)M_TOT * RANK];

// ------------- helpers -------------
__device__ __forceinline__ uint32_t smem_u32(const void* p) {
    uint32_t a;
    asm("{ .reg .u64 t; cvta.to.shared.u64 t, %1; cvt.u32.u64 %0, t; }" : "=r"(a) : "l"(p));
    return a;
}
__device__ __forceinline__ void ldsm4(uint32_t r[4], uint32_t addr) {
    asm volatile("ldmatrix.sync.aligned.m8n8.x4.shared.b16 {%0,%1,%2,%3}, [%4];"
                 : "=r"(r[0]), "=r"(r[1]), "=r"(r[2]), "=r"(r[3]) : "r"(addr));
}
__device__ __forceinline__ void mma_bf16(float c[4], const uint32_t a[4],
                                         uint32_t b0, uint32_t b1) {
    asm volatile(
        "mma.sync.aligned.m16n8k16.row.col.f32.bf16.bf16.f32 "
        "{%0,%1,%2,%3}, {%4,%5,%6,%7}, {%8,%9}, {%0,%1,%2,%3};"
        : "+f"(c[0]), "+f"(c[1]), "+f"(c[2]), "+f"(c[3])
        : "r"(a[0]), "r"(a[1]), "r"(a[2]), "r"(a[3]), "r"(b0), "r"(b1));
}
__device__ __forceinline__ uint32_t pk(__nv_bfloat16 a, __nv_bfloat16 b) {
    return (uint32_t)__bfloat16_as_ushort(a) | ((uint32_t)__bfloat16_as_ushort(b) << 16);
}
__device__ __forceinline__ uint32_t sw128(uint32_t b) {
    return b ^ ((b >> 3) & 0x70);
}

// Load 128x64 fp32 tile (row stride ld) -> bf16 hi & lo SW128 tiles. 512 threads.
__device__ __forceinline__ void load_cvt(const float* __restrict__ g, int ld,
                                         char* __restrict__ hi, char* __restrict__ lo,
                                         int tid) {
    #pragma unroll
    for (int it = 0; it < 4; ++it) {
        int idx = tid + it * 512;
        int row = idx >> 4;
        int c4  = (idx & 15) << 2;
        float4 v = *reinterpret_cast<const float4*>(g + (size_t)row * ld + c4);
        __nv_bfloat16 h0 = __float2bfloat16(v.x);
        __nv_bfloat16 h1 = __float2bfloat16(v.y);
        __nv_bfloat16 h2 = __float2bfloat16(v.z);
        __nv_bfloat16 h3 = __float2bfloat16(v.w);
        __nv_bfloat16 l0 = __float2bfloat16(v.x - __bfloat162float(h0));
        __nv_bfloat16 l1 = __float2bfloat16(v.y - __bfloat162float(h1));
        __nv_bfloat16 l2 = __float2bfloat16(v.z - __bfloat162float(h2));
        __nv_bfloat16 l3 = __float2bfloat16(v.w - __bfloat162float(h3));
        uint32_t off = sw128((uint32_t)(row * 128 + c4 * 2));
        uint2 hv; hv.x = pk(h0, h1); hv.y = pk(h2, h3);
        uint2 lv; lv.x = pk(l0, l1); lv.y = pk(l2, l3);
        *reinterpret_cast<uint2*>(hi + off) = hv;
        *reinterpret_cast<uint2*>(lo + off) = lv;
    }
}

// GEMM-NT: Out[m][n] = (sum_k X[m][k] * W[n][k]) * csc[n] * scale
// CTA tile 128x128, K-chunk 64, bf16x3 split precision on mma.sync,
// double-buffered SMEM. 512 threads = 16 warps as 4(m) x 4(n); warp tile 32x32.
__global__ __launch_bounds__(512, 1)
void vera_hmma(const float* __restrict__ X, const float* __restrict__ W,
               const float* __restrict__ csc, float scale, float* __restrict__ Out,
               int Ntot, int K)
{
    extern __shared__ char smem[];
    constexpr int STAGE = 65536;    // {Xhi,Xlo,Whi,Wlo} x 16KB
    float* cs = reinterpret_cast<float*>(smem + 2 * STAGE);
    const uint32_t sb = smem_u32(smem);

    const int tid = threadIdx.x;
    const int wid = tid >> 5;
    const int lid = tid & 31;
    const int warp_m = wid & 3;       // 4 warps along M (32 rows each)
    const int warp_n = wid >> 2;      // 4 warps along N (32 cols each)

    const int bm = blockIdx.x * 128;
    const int bn = blockIdx.y * 128;

    if (tid < 128) cs[tid] = csc[bn + tid] * scale;

    // per-lane ldmatrix offsets (within a stage)
    const int rowA = warp_m * 32 + (lid & 15);
    const uint32_t pA0 = (uint32_t)(rowA * 128);
    const uint32_t pA1 = pA0 + 16 * 128;
    const uint32_t kbA = (uint32_t)((lid >> 4) * 16);
    const uint32_t xA  = (uint32_t)((rowA & 7) << 4);
    const int rowB = warp_n * 32 + ((lid >> 4) * 8 + (lid & 7));
    const uint32_t pB0 = (uint32_t)(rowB * 128);
    const uint32_t kbB = (uint32_t)(((lid >> 3) & 1) * 16);
    const uint32_t xB  = (uint32_t)((rowB & 7) << 4);

    float acc[2][4][4];
    #pragma unroll
    for (int i = 0; i < 2; ++i)
        #pragma unroll
        for (int j = 0; j < 4; ++j)
            #pragma unroll
            for (int q = 0; q < 4; ++q)
                acc[i][j][q] = 0.0f;

    const int nchunks = K >> 6;
    const float* Xg = X + (size_t)bm * K;
    const float* Wg = W + (size_t)bn * K;

    // prologue: fill stage 0
    load_cvt(Xg, K, smem, smem + 16384, tid);
    load_cvt(Wg, K, smem + 32768, smem + 49152, tid);
    __syncthreads();

    for (int ch = 0; ch < nchunks; ++ch) {
        const int b = ch & 1;

        // producer for chunk ch+1 into the other stage
        if (ch + 1 < nchunks) {
            char* dst = smem + (b ^ 1) * STAGE;
            load_cvt(Xg + (ch + 1) * 64, K, dst, dst + 16384, tid);
            load_cvt(Wg + (ch + 1) * 64, K, dst + 32768, dst + 49152, tid);
        }

        // consumer on stage b
        const uint32_t base = sb + (uint32_t)(b * STAGE);
        #pragma unroll
        for (int s = 0; s < 4; ++s) {
            const uint32_t aoff = ((uint32_t)(s * 32) + kbA) ^ xA;
            const uint32_t boff = ((uint32_t)(s * 32) + kbB) ^ xB;
            uint32_t ah0[4], ah1[4], al0[4], al1[4];
            ldsm4(ah0, base + 0     + pA0 + aoff);
            ldsm4(ah1, base + 0     + pA1 + aoff);
            ldsm4(al0, base + 16384 + pA0 + aoff);
            ldsm4(al1, base + 16384 + pA1 + aoff);
            #pragma unroll
            for (int np = 0; np < 2; ++np) {
                uint32_t bh[4], bl[4];
                ldsm4(bh, base + 32768 + pB0 + (uint32_t)(np * 2048) + boff);
                ldsm4(bl, base + 49152 + pB0 + (uint32_t)(np * 2048) + boff);
                mma_bf16(acc[0][2 * np],     ah0, bh[0], bh[1]);
                mma_bf16(acc[1][2 * np],     ah1, bh[0], bh[1]);
                mma_bf16(acc[0][2 * np + 1], ah0, bh[2], bh[3]);
                mma_bf16(acc[1][2 * np + 1], ah1, bh[2], bh[3]);
                mma_bf16(acc[0][2 * np],     ah0, bl[0], bl[1]);
                mma_bf16(acc[1][2 * np],     ah1, bl[0], bl[1]);
                mma_bf16(acc[0][2 * np + 1], ah0, bl[2], bl[3]);
                mma_bf16(acc[1][2 * np + 1], ah1, bl[2], bl[3]);
                mma_bf16(acc[0][2 * np],     al0, bh[0], bh[1]);
                mma_bf16(acc[1][2 * np],     al1, bh[0], bh[1]);
                mma_bf16(acc[0][2 * np + 1], al0, bh[2], bh[3]);
                mma_bf16(acc[1][2 * np + 1], al1, bh[2], bh[3]);
            }
        }
        __syncthreads();
    }

    // epilogue
    const int mrow0 = bm + warp_m * 32 + (lid >> 2);
    const int nc0   = warp_n * 32 + (lid & 3) * 2;
    #pragma unroll
    for (int mi = 0; mi < 2; ++mi) {
        #pragma unroll
        for (int nj = 0; nj < 4; ++nj) {
            const int n = nc0 + nj * 8;
            const float s0 = cs[n], s1 = cs[n + 1];
            float2 v0, v1;
            v0.x = acc[mi][nj][0] * s0; v0.y = acc[mi][nj][1] * s1;
            v1.x = acc[mi][nj][2] * s0; v1.y = acc[mi][nj][3] * s1;
            const int m0 = mrow0 + mi * 16;
            *reinterpret_cast<float2*>(Out + (size_t)m0 * Ntot + bn + n) = v0;
            *reinterpret_cast<float2*>(Out + (size_t)(m0 + 8) * Ntot + bn + n) = v1;
        }
    }
}

extern "C" void kernel_launch(void* const* d_in, const int* in_sizes, int n_in,
                              void* d_out, int out_size)
{
    const float* x   = (const float*)d_in[0];  // [8192][4096]
    const float* A   = (const float*)d_in[1];  // [256][4096]
    const float* B   = (const float*)d_in[2];  // [4096][256]
    const float* d_A = (const float*)d_in[3];  // [256]
    const float* d_B = (const float*)d_in[4];  // [4096]
    float* out = (float*)d_out;                // [8192][4096]

    float* t = nullptr;
    cudaGetSymbolAddress((void**)&t, g_t);

    constexpr int SMEM = 2 * 65536 + 512;      // 131584
    cudaFuncSetAttribute(vera_hmma, cudaFuncAttributeMaxDynamicSharedMemorySize, SMEM);

    // GEMM1: t = (x @ A^T) * d_A      M=8192, N=256, K=4096
    {
        dim3 grid(M_TOT / 128, RANK / 128);   // 64 x 2
        vera_hmma<<<grid, 512, SMEM>>>(x, A, d_A, 1.0f, t, RANK, K_IN);
    }
    // GEMM2: out = (t @ B^T) * d_B * SCALE   M=8192, N=4096, K=256
    {
        dim3 grid(M_TOT / 128, N_OUT / 128);  // 64 x 32
        vera_hmma<<<grid, 512, SMEM>>>(t, B, d_B, VERA_SCALE, out, N_OUT, RANK);
    }
}

// round 6
// speedup vs baseline: 1.2838x; 1.1650x over previous
#include <cuda_runtime.h>
#include <cuda_bf16.h>
#include <cstdint>

#define M_TOT   8192
#define K_IN    4096
#define RANK    256
#define N_OUT   4096
#define VERA_SCALE (32.0f / 256.0f)

// rank-space intermediate t = (x @ A^T) * d_A : [M_TOT][RANK]
__device__ float g_t[(size_t)M_TOT * RANK];

// ------------- helpers -------------
__device__ __forceinline__ uint32_t smem_u32(const void* p) {
    uint32_t a;
    asm("{ .reg .u64 t; cvta.to.shared.u64 t, %1; cvt.u32.u64 %0, t; }" : "=r"(a) : "l"(p));
    return a;
}
__device__ __forceinline__ void ldsm4(uint32_t r[4], uint32_t addr) {
    asm volatile("ldmatrix.sync.aligned.m8n8.x4.shared.b16 {%0,%1,%2,%3}, [%4];"
                 : "=r"(r[0]), "=r"(r[1]), "=r"(r[2]), "=r"(r[3]) : "r"(addr));
}
__device__ __forceinline__ void mma_bf16(float c[4], const uint32_t a[4],
                                         uint32_t b0, uint32_t b1) {
    asm volatile(
        "mma.sync.aligned.m16n8k16.row.col.f32.bf16.bf16.f32 "
        "{%0,%1,%2,%3}, {%4,%5,%6,%7}, {%8,%9}, {%0,%1,%2,%3};"
        : "+f"(c[0]), "+f"(c[1]), "+f"(c[2]), "+f"(c[3])
        : "r"(a[0]), "r"(a[1]), "r"(a[2]), "r"(a[3]), "r"(b0), "r"(b1));
}
__device__ __forceinline__ uint32_t sw128(uint32_t b) {
    return b ^ ((b >> 3) & 0x70);
}
// Split a pair of fp32 into packed-bf16 hi (truncated top-16) and lo (residual).
__device__ __forceinline__ void split2(float a, float b, uint32_t& hi, uint32_t& lo) {
    uint32_t ua = __float_as_uint(a), ub = __float_as_uint(b);
    hi = __byte_perm(ua, ub, 0x7632);               // {trunc-bf16(a), trunc-bf16(b)}
    float fa = __uint_as_float(ua & 0xFFFF0000u);
    float fb = __uint_as_float(ub & 0xFFFF0000u);
    float la = a - fa, lb = b - fb;                 // exact residuals
    asm("cvt.rn.bf16x2.f32 %0, %1, %2;" : "=r"(lo) : "f"(lb), "f"(la));
}

// Full 128x64 fp32 -> hi/lo bf16 SW128 tiles (prologue only). 256 threads.
__device__ __forceinline__ void load_cvt(const float* __restrict__ g, int ld,
                                         char* __restrict__ hi, char* __restrict__ lo,
                                         int tid) {
    #pragma unroll
    for (int it = 0; it < 8; ++it) {
        int idx = tid + it * 256;
        int row = idx >> 4;
        int c4  = (idx & 15) << 2;
        float4 v = *reinterpret_cast<const float4*>(g + (size_t)row * ld + c4);
        uint32_t h0, l0, h1, l1;
        split2(v.x, v.y, h0, l0);
        split2(v.z, v.w, h1, l1);
        uint32_t off = sw128((uint32_t)(row * 128 + c4 * 2));
        *reinterpret_cast<uint2*>(hi + off) = make_uint2(h0, h1);
        *reinterpret_cast<uint2*>(lo + off) = make_uint2(l0, l1);
    }
}

// Quarter-chunk producer: group g covers rows [32g, 32g+32) of both tiles.
__device__ __forceinline__ void ldg_group(const float* __restrict__ X,
                                          const float* __restrict__ W, int ld,
                                          int g, int tid, float4 xs[2], float4 ws[2]) {
    #pragma unroll
    for (int j = 0; j < 2; ++j) {
        int idx = tid + (2 * g + j) * 256;
        int row = idx >> 4;
        int c4  = (idx & 15) << 2;
        xs[j] = *reinterpret_cast<const float4*>(X + (size_t)row * ld + c4);
        ws[j] = *reinterpret_cast<const float4*>(W + (size_t)row * ld + c4);
    }
}
__device__ __forceinline__ void cvt_sts_group(char* __restrict__ dst, int g, int tid,
                                              const float4 xs[2], const float4 ws[2]) {
    #pragma unroll
    for (int j = 0; j < 2; ++j) {
        int idx = tid + (2 * g + j) * 256;
        int row = idx >> 4;
        int c4  = (idx & 15) << 2;
        uint32_t off = sw128((uint32_t)(row * 128 + c4 * 2));
        uint32_t h0, l0, h1, l1;
        split2(xs[j].x, xs[j].y, h0, l0);
        split2(xs[j].z, xs[j].w, h1, l1);
        *reinterpret_cast<uint2*>(dst + off)         = make_uint2(h0, h1);
        *reinterpret_cast<uint2*>(dst + 16384 + off) = make_uint2(l0, l1);
        split2(ws[j].x, ws[j].y, h0, l0);
        split2(ws[j].z, ws[j].w, h1, l1);
        *reinterpret_cast<uint2*>(dst + 32768 + off) = make_uint2(h0, h1);
        *reinterpret_cast<uint2*>(dst + 49152 + off) = make_uint2(l0, l1);
    }
}

// GEMM-NT: Out[m][n] = (sum_k X[m][k] * W[n][k]) * csc[n] * scale
// CTA 128x128, K-chunk 64, bf16x3 on mma.sync. 256 threads = 8 warps (4m x 2n),
// warp tile 32x64. Producer (LDG/cvt/STS for next chunk) interleaved at s-step
// granularity inside the MMA stream so DRAM latency hides behind HMMAs.
__global__ __launch_bounds__(256, 1)
void vera_hmma(const float* __restrict__ X, const float* __restrict__ W,
               const float* __restrict__ csc, float scale, float* __restrict__ Out,
               int Ntot, int K)
{
    extern __shared__ char smem[];
    constexpr int STAGE = 65536;   // {Xhi,Xlo,Whi,Wlo} x 16KB
    float* cs = reinterpret_cast<float*>(smem + 2 * STAGE);
    const uint32_t sb = smem_u32(smem);

    const int tid = threadIdx.x;
    const int wid = tid >> 5;
    const int lid = tid & 31;
    const int warp_m = wid & 3;
    const int warp_n = wid >> 2;

    const int bm = blockIdx.x * 128;
    const int bn = blockIdx.y * 128;

    if (tid < 128) cs[tid] = csc[bn + tid] * scale;

    const int rowA = warp_m * 32 + (lid & 15);
    const uint32_t pA0 = (uint32_t)(rowA * 128);
    const uint32_t pA1 = pA0 + 16 * 128;
    const uint32_t kbA = (uint32_t)((lid >> 4) * 16);
    const uint32_t xA  = (uint32_t)((rowA & 7) << 4);
    const int rowB = warp_n * 64 + ((lid >> 4) * 8 + (lid & 7));
    const uint32_t pB0 = (uint32_t)(rowB * 128);
    const uint32_t kbB = (uint32_t)(((lid >> 3) & 1) * 16);
    const uint32_t xB  = (uint32_t)((rowB & 7) << 4);

    float acc[2][8][4];
    #pragma unroll
    for (int i = 0; i < 2; ++i)
        #pragma unroll
        for (int j = 0; j < 8; ++j)
            #pragma unroll
            for (int q = 0; q < 4; ++q)
                acc[i][j][q] = 0.0f;

    const int nchunks = K >> 6;
    const float* Xg = X + (size_t)bm * K;
    const float* Wg = W + (size_t)bn * K;

    // prologue: fill stage 0
    load_cvt(Xg, K, smem, smem + 16384, tid);
    load_cvt(Wg, K, smem + 32768, smem + 49152, tid);
    __syncthreads();

    for (int ch = 0; ch < nchunks; ++ch) {
        const int b = ch & 1;
        const uint32_t base = sb + (uint32_t)(b * STAGE);
        char* dst = smem + (b ^ 1) * STAGE;
        const bool more = (ch + 1 < nchunks);
        const float* Xn = Xg + (ch + 1) * 64;
        const float* Wn = Wg + (ch + 1) * 64;

        #pragma unroll
        for (int s = 0; s < 4; ++s) {
            float4 xs[2], ws[2];
            if (more) ldg_group(Xn, Wn, K, s, tid, xs, ws);   // issue LDGs

            // ---- MMA s-step on stage b ----
            const uint32_t aoff = ((uint32_t)(s * 32) + kbA) ^ xA;
            const uint32_t boff = ((uint32_t)(s * 32) + kbB) ^ xB;
            uint32_t ah0[4], ah1[4], al0[4], al1[4];
            ldsm4(ah0, base + 0     + pA0 + aoff);
            ldsm4(ah1, base + 0     + pA1 + aoff);
            ldsm4(al0, base + 16384 + pA0 + aoff);
            ldsm4(al1, base + 16384 + pA1 + aoff);
            #pragma unroll
            for (int np = 0; np < 4; ++np) {
                uint32_t bh[4], bl[4];
                ldsm4(bh, base + 32768 + pB0 + (uint32_t)(np * 2048) + boff);
                ldsm4(bl, base + 49152 + pB0 + (uint32_t)(np * 2048) + boff);
                mma_bf16(acc[0][2 * np],     ah0, bh[0], bh[1]);
                mma_bf16(acc[1][2 * np],     ah1, bh[0], bh[1]);
                mma_bf16(acc[0][2 * np + 1], ah0, bh[2], bh[3]);
                mma_bf16(acc[1][2 * np + 1], ah1, bh[2], bh[3]);
                mma_bf16(acc[0][2 * np],     ah0, bl[0], bl[1]);
                mma_bf16(acc[1][2 * np],     ah1, bl[0], bl[1]);
                mma_bf16(acc[0][2 * np + 1], ah0, bl[2], bl[3]);
                mma_bf16(acc[1][2 * np + 1], ah1, bl[2], bl[3]);
                mma_bf16(acc[0][2 * np],     al0, bh[0], bh[1]);
                mma_bf16(acc[1][2 * np],     al1, bh[0], bh[1]);
                mma_bf16(acc[0][2 * np + 1], al0, bh[2], bh[3]);
                mma_bf16(acc[1][2 * np + 1], al1, bh[2], bh[3]);
            }

            if (more) cvt_sts_group(dst, s, tid, xs, ws);     // consume LDGs
        }
        __syncthreads();
    }

    // epilogue
    const int mrow0 = bm + warp_m * 32 + (lid >> 2);
    const int nc0   = warp_n * 64 + (lid & 3) * 2;
    #pragma unroll
    for (int mi = 0; mi < 2; ++mi) {
        #pragma unroll
        for (int nj = 0; nj < 8; ++nj) {
            const int n = nc0 + nj * 8;
            const float s0 = cs[n], s1 = cs[n + 1];
            float2 v0, v1;
            v0.x = acc[mi][nj][0] * s0; v0.y = acc[mi][nj][1] * s1;
            v1.x = acc[mi][nj][2] * s0; v1.y = acc[mi][nj][3] * s1;
            const int m0 = mrow0 + mi * 16;
            *reinterpret_cast<float2*>(Out + (size_t)m0 * Ntot + bn + n) = v0;
            *reinterpret_cast<float2*>(Out + (size_t)(m0 + 8) * Ntot + bn + n) = v1;
        }
    }
}

extern "C" void kernel_launch(void* const* d_in, const int* in_sizes, int n_in,
                              void* d_out, int out_size)
{
    const float* x   = (const float*)d_in[0];  // [8192][4096]
    const float* A   = (const float*)d_in[1];  // [256][4096]
    const float* B   = (const float*)d_in[2];  // [4096][256]
    const float* d_A = (const float*)d_in[3];  // [256]
    const float* d_B = (const float*)d_in[4];  // [4096]
    float* out = (float*)d_out;                // [8192][4096]

    float* t = nullptr;
    cudaGetSymbolAddress((void**)&t, g_t);

    constexpr int SMEM = 2 * 65536 + 512;      // 131584
    cudaFuncSetAttribute(vera_hmma, cudaFuncAttributeMaxDynamicSharedMemorySize, SMEM);

    // GEMM1: t = (x @ A^T) * d_A      M=8192, N=256, K=4096
    {
        dim3 grid(M_TOT / 128, RANK / 128);   // 64 x 2
        vera_hmma<<<grid, 256, SMEM>>>(x, A, d_A, 1.0f, t, RANK, K_IN);
    }
    // GEMM2: out = (t @ B^T) * d_B * SCALE   M=8192, N=4096, K=256
    {
        dim3 grid(M_TOT / 128, N_OUT / 128);  // 64 x 32
        vera_hmma<<<grid, 256, SMEM>>>(t, B, d_B, VERA_SCALE, out, N_OUT, RANK);
    }
}

// round 7
// speedup vs baseline: 1.3037x; 1.0155x over previous
#include <cuda_runtime.h>
#include <cuda_bf16.h>
#include <cstdint>

#define M_TOT   8192
#define K_IN    4096
#define RANK    256
#define N_OUT   4096
#define VERA_SCALE (32.0f / 256.0f)

// rank-space intermediate t = (x @ A^T) * d_A : [M_TOT][RANK]
__device__ float g_t[(size_t)M_TOT * RANK];

// ------------- helpers -------------
__device__ __forceinline__ uint32_t smem_u32(const void* p) {
    uint32_t a;
    asm("{ .reg .u64 t; cvta.to.shared.u64 t, %1; cvt.u32.u64 %0, t; }" : "=r"(a) : "l"(p));
    return a;
}
__device__ __forceinline__ void ldsm4(uint32_t r[4], uint32_t addr) {
    asm volatile("ldmatrix.sync.aligned.m8n8.x4.shared.b16 {%0,%1,%2,%3}, [%4];"
                 : "=r"(r[0]), "=r"(r[1]), "=r"(r[2]), "=r"(r[3]) : "r"(addr));
}
__device__ __forceinline__ void mma_bf16(float c[4], const uint32_t a[4],
                                         uint32_t b0, uint32_t b1) {
    asm volatile(
        "mma.sync.aligned.m16n8k16.row.col.f32.bf16.bf16.f32 "
        "{%0,%1,%2,%3}, {%4,%5,%6,%7}, {%8,%9}, {%0,%1,%2,%3};"
        : "+f"(c[0]), "+f"(c[1]), "+f"(c[2]), "+f"(c[3])
        : "r"(a[0]), "r"(a[1]), "r"(a[2]), "r"(a[3]), "r"(b0), "r"(b1));
}
__device__ __forceinline__ uint32_t sw128(uint32_t b) {
    return b ^ ((b >> 3) & 0x70);
}
// Split a pair of fp32 into packed-bf16 hi (truncated top-16) and lo (residual).
__device__ __forceinline__ void split2(float a, float b, uint32_t& hi, uint32_t& lo) {
    uint32_t ua = __float_as_uint(a), ub = __float_as_uint(b);
    hi = __byte_perm(ua, ub, 0x7632);               // {trunc-bf16(a), trunc-bf16(b)}
    float fa = __uint_as_float(ua & 0xFFFF0000u);
    float fb = __uint_as_float(ub & 0xFFFF0000u);
    float la = a - fa, lb = b - fb;                 // exact residuals
    asm("cvt.rn.bf16x2.f32 %0, %1, %2;" : "=r"(lo) : "f"(lb), "f"(la));
}

// Full 128x64 fp32 -> hi/lo bf16 SW128 tiles (prologue). 512 threads.
__device__ __forceinline__ void load_cvt(const float* __restrict__ g, int ld,
                                         char* __restrict__ hi, char* __restrict__ lo,
                                         int tid) {
    #pragma unroll
    for (int it = 0; it < 4; ++it) {
        int idx = tid + it * 512;
        int row = idx >> 4;
        int c4  = (idx & 15) << 2;
        float4 v = *reinterpret_cast<const float4*>(g + (size_t)row * ld + c4);
        uint32_t h0, l0, h1, l1;
        split2(v.x, v.y, h0, l0);
        split2(v.z, v.w, h1, l1);
        uint32_t off = sw128((uint32_t)(row * 128 + c4 * 2));
        *reinterpret_cast<uint2*>(hi + off) = make_uint2(h0, h1);
        *reinterpret_cast<uint2*>(lo + off) = make_uint2(l0, l1);
    }
}

// GEMM-NT: Out[m][n] = (sum_k X[m][k] * W[n][k]) * csc[n] * scale
// CTA 128x128, K-chunk 64, bf16x3 on mma.sync. 512 threads = 16 warps (4m x 4n),
// warp tile 32x32. Producer (LDG/cvt/STS for next chunk) interleaved at s-step
// granularity inside the MMA stream so DRAM latency hides behind HMMAs.
__global__ __launch_bounds__(512, 1)
void vera_hmma(const float* __restrict__ X, const float* __restrict__ W,
               const float* __restrict__ csc, float scale, float* __restrict__ Out,
               int Ntot, int K)
{
    extern __shared__ char smem[];
    constexpr int STAGE = 65536;   // {Xhi,Xlo,Whi,Wlo} x 16KB
    float* cs = reinterpret_cast<float*>(smem + 2 * STAGE);
    const uint32_t sb = smem_u32(smem);

    const int tid = threadIdx.x;
    const int wid = tid >> 5;
    const int lid = tid & 31;
    const int warp_m = wid & 3;     // 4 warps along M
    const int warp_n = wid >> 2;    // 4 warps along N

    const int bm = blockIdx.x * 128;
    const int bn = blockIdx.y * 128;

    if (tid < 128) cs[tid] = csc[bn + tid] * scale;

    const int rowA = warp_m * 32 + (lid & 15);
    const uint32_t pA0 = (uint32_t)(rowA * 128);
    const uint32_t pA1 = pA0 + 16 * 128;
    const uint32_t kbA = (uint32_t)((lid >> 4) * 16);
    const uint32_t xA  = (uint32_t)((rowA & 7) << 4);
    const int rowB = warp_n * 32 + ((lid >> 4) * 8 + (lid & 7));
    const uint32_t pB0 = (uint32_t)(rowB * 128);
    const uint32_t kbB = (uint32_t)(((lid >> 3) & 1) * 16);
    const uint32_t xB  = (uint32_t)((rowB & 7) << 4);

    // producer addressing: per s-step this thread handles idx = tid + s*512
    const int prow = tid >> 4;            // base row within 32-row group: varies per s
    const int pc4  = (tid & 15) << 2;
    (void)prow;

    float acc[2][4][4];
    #pragma unroll
    for (int i = 0; i < 2; ++i)
        #pragma unroll
        for (int j = 0; j < 4; ++j)
            #pragma unroll
            for (int q = 0; q < 4; ++q)
                acc[i][j][q] = 0.0f;

    const int nchunks = K >> 6;
    const float* Xg = X + (size_t)bm * K;
    const float* Wg = W + (size_t)bn * K;

    // prologue: fill stage 0
    load_cvt(Xg, K, smem, smem + 16384, tid);
    load_cvt(Wg, K, smem + 32768, smem + 49152, tid);
    __syncthreads();

    for (int ch = 0; ch < nchunks; ++ch) {
        const int b = ch & 1;
        const uint32_t base = sb + (uint32_t)(b * STAGE);
        char* dst = smem + (b ^ 1) * STAGE;
        const bool more = (ch + 1 < nchunks);
        const float* Xn = Xg + (ch + 1) * 64;
        const float* Wn = Wg + (ch + 1) * 64;

        #pragma unroll
        for (int s = 0; s < 4; ++s) {
            // issue next-chunk LDGs for this thread's slice of group s
            const int idx = tid + s * 512;
            const int row = idx >> 4;
            float4 xv, wv;
            if (more) {
                xv = *reinterpret_cast<const float4*>(Xn + (size_t)row * K + pc4);
                wv = *reinterpret_cast<const float4*>(Wn + (size_t)row * K + pc4);
            }

            // ---- MMA s-step on stage b ----
            const uint32_t aoff = ((uint32_t)(s * 32) + kbA) ^ xA;
            const uint32_t boff = ((uint32_t)(s * 32) + kbB) ^ xB;
            uint32_t ah0[4], ah1[4], al0[4], al1[4];
            ldsm4(ah0, base + 0     + pA0 + aoff);
            ldsm4(ah1, base + 0     + pA1 + aoff);
            ldsm4(al0, base + 16384 + pA0 + aoff);
            ldsm4(al1, base + 16384 + pA1 + aoff);
            #pragma unroll
            for (int np = 0; np < 2; ++np) {
                uint32_t bh[4], bl[4];
                ldsm4(bh, base + 32768 + pB0 + (uint32_t)(np * 2048) + boff);
                ldsm4(bl, base + 49152 + pB0 + (uint32_t)(np * 2048) + boff);
                mma_bf16(acc[0][2 * np],     ah0, bh[0], bh[1]);
                mma_bf16(acc[1][2 * np],     ah1, bh[0], bh[1]);
                mma_bf16(acc[0][2 * np + 1], ah0, bh[2], bh[3]);
                mma_bf16(acc[1][2 * np + 1], ah1, bh[2], bh[3]);
                mma_bf16(acc[0][2 * np],     ah0, bl[0], bl[1]);
                mma_bf16(acc[1][2 * np],     ah1, bl[0], bl[1]);
                mma_bf16(acc[0][2 * np + 1], ah0, bl[2], bl[3]);
                mma_bf16(acc[1][2 * np + 1], ah1, bl[2], bl[3]);
                mma_bf16(acc[0][2 * np],     al0, bh[0], bh[1]);
                mma_bf16(acc[1][2 * np],     al1, bh[0], bh[1]);
                mma_bf16(acc[0][2 * np + 1], al0, bh[2], bh[3]);
                mma_bf16(acc[1][2 * np + 1], al1, bh[2], bh[3]);
            }

            // consume LDGs: cvt + STS into the other stage
            if (more) {
                const uint32_t off = sw128((uint32_t)(row * 128 + pc4 * 2));
                uint32_t h0, l0, h1, l1;
                split2(xv.x, xv.y, h0, l0);
                split2(xv.z, xv.w, h1, l1);
                *reinterpret_cast<uint2*>(dst + off)         = make_uint2(h0, h1);
                *reinterpret_cast<uint2*>(dst + 16384 + off) = make_uint2(l0, l1);
                split2(wv.x, wv.y, h0, l0);
                split2(wv.z, wv.w, h1, l1);
                *reinterpret_cast<uint2*>(dst + 32768 + off) = make_uint2(h0, h1);
                *reinterpret_cast<uint2*>(dst + 49152 + off) = make_uint2(l0, l1);
            }
        }
        __syncthreads();
    }

    // epilogue
    const int mrow0 = bm + warp_m * 32 + (lid >> 2);
    const int nc0   = warp_n * 32 + (lid & 3) * 2;
    #pragma unroll
    for (int mi = 0; mi < 2; ++mi) {
        #pragma unroll
        for (int nj = 0; nj < 4; ++nj) {
            const int n = nc0 + nj * 8;
            const float s0 = cs[n], s1 = cs[n + 1];
            float2 v0, v1;
            v0.x = acc[mi][nj][0] * s0; v0.y = acc[mi][nj][1] * s1;
            v1.x = acc[mi][nj][2] * s0; v1.y = acc[mi][nj][3] * s1;
            const int m0 = mrow0 + mi * 16;
            *reinterpret_cast<float2*>(Out + (size_t)m0 * Ntot + bn + n) = v0;
            *reinterpret_cast<float2*>(Out + (size_t)(m0 + 8) * Ntot + bn + n) = v1;
        }
    }
}

extern "C" void kernel_launch(void* const* d_in, const int* in_sizes, int n_in,
                              void* d_out, int out_size)
{
    const float* x   = (const float*)d_in[0];  // [8192][4096]
    const float* A   = (const float*)d_in[1];  // [256][4096]
    const float* B   = (const float*)d_in[2];  // [4096][256]
    const float* d_A = (const float*)d_in[3];  // [256]
    const float* d_B = (const float*)d_in[4];  // [4096]
    float* out = (float*)d_out;                // [8192][4096]

    float* t = nullptr;
    cudaGetSymbolAddress((void**)&t, g_t);

    constexpr int SMEM = 2 * 65536 + 512;      // 131584
    cudaFuncSetAttribute(vera_hmma, cudaFuncAttributeMaxDynamicSharedMemorySize, SMEM);

    // GEMM1: t = (x @ A^T) * d_A      M=8192, N=256, K=4096
    {
        dim3 grid(M_TOT / 128, RANK / 128);   // 64 x 2
        vera_hmma<<<grid, 512, SMEM>>>(x, A, d_A, 1.0f, t, RANK, K_IN);
    }
    // GEMM2: out = (t @ B^T) * d_B * SCALE   M=8192, N=4096, K=256
    {
        dim3 grid(M_TOT / 128, N_OUT / 128);  // 64 x 32
        vera_hmma<<<grid, 512, SMEM>>>(t, B, d_B, VERA_SCALE, out, N_OUT, RANK);
    }
}